// round 9
// baseline (speedup 1.0000x reference)
#include <cuda_runtime.h>
#include <cuda_fp16.h>
#include <math.h>
#include <stdint.h>

#define Bn   64
#define Cc   128
#define Hh   56
#define Ww   56
#define HW   3136
#define NTOT 25690112
#define WN   147456
#define NSTAT 200704
#define PIMG 430592ull            // 3364*128 elems per padded image plane
#define TOTS 27585536ull          // 8192 front guard + 64*PIMG + 19456 back guard
#define NTILE 27                  // ceil(3364/128)
#define NPIX 3364                 // 58*58
#define CIMG 430592ull            // per-image floats in NHWC out buffers

// ---------------- device scratch ----------------
__device__ uint8_t g_planes[4ull * TOTS];        // limb0, limb1, limb2, a1-levels
__device__ __half  g_xh[TOTS];                   // x fp16, padded NHWC
__device__ signed char g_w1s[9 * Cc * Cc];       // [k][co][ci] s8 = 15*w1q-int
__device__ __half  g_w1d[9 * Cc * Cc];           // [k][co][ci] fp16 = (w_ref - wInt/15)*2^20
__device__ signed char g_w2s[9 * Cc * Cc];       // [k][co][ci] s8 = 15*w2q-int
__device__ float  g_c0[Bn * CIMG];               // NHWC padded GEMM outputs
__device__ float  g_c1[Bn * CIMG];
__device__ float  g_c2[Bn * CIMG];
__device__ float  g_c3[Bn * CIMG];               // fp16 correction GEMM output
__device__ double g_sum[2][Cc];
__device__ double g_sq[2][Cc];
__device__ float  g_mean[2][Cc];
__device__ float  g_rs[2][Cc];
__device__ unsigned g_maxbits[2];

// ---------------- math helpers ----------------
__device__ __forceinline__ float xla_tanh(float x) {
    if (fabsf(x) < 0.0004f) return x;
    float xc = fminf(fmaxf(x, -7.90531110763549805f), 7.90531110763549805f);
    float x2 = __fmul_rn(xc, xc);
    float np = -2.76076847742355e-16f;
    np = fmaf(np, x2, 2.00018790482477e-13f);
    np = fmaf(np, x2, -8.60467152213735e-11f);
    np = fmaf(np, x2, 5.12229709037114e-08f);
    np = fmaf(np, x2, 1.48572235717979e-05f);
    np = fmaf(np, x2, 6.37261928875436e-04f);
    np = fmaf(np, x2, 4.89352455891786e-03f);
    np = __fmul_rn(xc, np);
    float dp = 1.19825839466702e-06f;
    dp = fmaf(dp, x2, 1.18534705686654e-04f);
    dp = fmaf(dp, x2, 2.26843463243900e-03f);
    dp = fmaf(dp, x2, 4.89352518554385e-03f);
    return __fdiv_rn(np, dp);
}
__device__ __forceinline__ float ste_quant(float c) {
    float q = __fdiv_rn(rintf(__fmul_rn(c, 15.0f)), 15.0f);
    return __fadd_rn(c, __fadd_rn(q, -c));
}
__device__ __forceinline__ void imma(int* d, const uint32_t* a, const uint32_t* b) {
    asm volatile(
        "mma.sync.aligned.m16n8k32.row.col.s32.u8.s8.s32 "
        "{%0,%1,%2,%3}, {%4,%5,%6,%7}, {%8,%9}, {%0,%1,%2,%3};"
        : "+r"(d[0]), "+r"(d[1]), "+r"(d[2]), "+r"(d[3])
        : "r"(a[0]), "r"(a[1]), "r"(a[2]), "r"(a[3]), "r"(b[0]), "r"(b[1]));
}
__device__ __forceinline__ void mmaf16(float* d, const uint32_t* a, const uint32_t* b) {
    asm volatile(
        "mma.sync.aligned.m16n8k16.row.col.f32.f16.f16.f32 "
        "{%0,%1,%2,%3}, {%4,%5,%6,%7}, {%8,%9}, {%0,%1,%2,%3};"
        : "+f"(d[0]), "+f"(d[1]), "+f"(d[2]), "+f"(d[3])
        : "r"(a[0]), "r"(a[1]), "r"(a[2]), "r"(a[3]), "r"(b[0]), "r"(b[1]));
}
// combine limb GEMMs + correction into the fp32 y1 value (shared by bnq/stats)
__device__ __forceinline__ float combine_y1(size_t off) {
    double sm = (double)g_c0[off] * 65536.0 + (double)g_c1[off] * 256.0 +
                (double)g_c2[off];
    double yv = sm * (1.0 / 125829120.0) +
                (double)g_c3[off] * (1.0 / 1048576.0);
    return (float)yv;
}

// ---------------- setup kernels ----------------
__global__ void k_zero() {
    int i = threadIdx.x;
    if (i < Cc) { g_sum[0][i]=0.0; g_sum[1][i]=0.0; g_sq[0][i]=0.0; g_sq[1][i]=0.0; }
    if (i < 2) g_maxbits[i] = 0u;
}
__global__ void k_zeroplanes() {
    size_t tot = 4ull * TOTS / 16;
    for (size_t i = (size_t)blockIdx.x * blockDim.x + threadIdx.x; i < tot;
         i += (size_t)gridDim.x * blockDim.x)
        ((uint4*)g_planes)[i] = make_uint4(0, 0, 0, 0);
    size_t tot2 = 2ull * TOTS / 16;
    for (size_t i = (size_t)blockIdx.x * blockDim.x + threadIdx.x; i < tot2;
         i += (size_t)gridDim.x * blockDim.x)
        ((uint4*)g_xh)[i] = make_uint4(0, 0, 0, 0);
}
__global__ void k_maxabs(const float* __restrict__ w1, const float* __restrict__ w2) {
    const int t = blockIdx.y;
    const float* w = t ? w2 : w1;
    float m = 0.0f;
    for (int i = blockIdx.x * blockDim.x + threadIdx.x; i < WN;
         i += gridDim.x * blockDim.x)
        m = fmaxf(m, fabsf(xla_tanh(w[i])));
    #pragma unroll
    for (int o = 16; o; o >>= 1) m = fmaxf(m, __shfl_xor_sync(0xffffffffu, m, o));
    if ((threadIdx.x & 31) == 0) atomicMax(&g_maxbits[t], __float_as_uint(m));
}
__global__ void k_quantw(const float* __restrict__ w1, const float* __restrict__ w2) {
    const int t = blockIdx.y;
    const float* w = t ? w2 : w1;
    const float M = __uint_as_float(g_maxbits[t]);
    const float twoM = __fmul_rn(2.0f, M);
    for (int i = blockIdx.x * blockDim.x + threadIdx.x; i < WN;
         i += gridDim.x * blockDim.x) {
        float tv = xla_tanh(w[i]);
        float wn = __fadd_rn(__fdiv_rn(tv, twoM), 0.5f);
        int lvl = (int)rintf(__fmul_rn(wn, 15.0f));   // 0..15
        int wInt = 2 * lvl - 15;
        int k = i % 9, ci = (i / 9) % Cc, co = i / (9 * Cc);
        size_t widx = ((size_t)k * Cc + co) * Cc + ci;
        if (t == 0) {
            g_w1s[widx] = (signed char)wInt;
            // ref-exact STE weight value and its delta vs wInt/15
            float st = ste_quant(wn);
            float ov = __fadd_rn(__fmul_rn(2.0f, st), -1.0f);
            double dd = (double)ov - (double)wInt / 15.0;
            g_w1d[widx] = __float2half_rn((float)(dd * 1048576.0));
        } else {
            g_w2s[widx] = (signed char)wInt;
        }
    }
}

// x NCHW fp32 -> 3 u8 limb planes + fp16 plane, padded NHWC. x = k*2^-23 exact.
__global__ void k_pack(const float* __restrict__ x) {
    __shared__ float tile[32][33];
    const int n = blockIdx.z, h = blockIdx.y;
    const int w0 = (blockIdx.x & 1) * 32, c0 = (blockIdx.x >> 1) * 32;
    const int tx = threadIdx.x, ty = threadIdx.y;
    float v = 0.0f;
    if (w0 + tx < Ww)
        v = x[((size_t)(n * Cc + c0 + ty)) * HW + h * Ww + w0 + tx];
    tile[ty][tx] = v;
    __syncthreads();
    int wp = w0 + ty;
    if (wp < Ww) {
        float val = tile[tx][ty];
        uint32_t k = (uint32_t)(val * 8388608.0f);    // exact
        size_t pix = (size_t)(h + 1) * 58 + (wp + 1);
        size_t off = 8192 + (size_t)n * PIMG + pix * 128 + c0 + tx;
        g_planes[off]               = (uint8_t)(k >> 16);
        g_planes[TOTS + off]        = (uint8_t)((k >> 8) & 0xFF);
        g_planes[2ull * TOTS + off] = (uint8_t)(k & 0xFF);
        g_xh[off] = __float2half_rn(val);
    }
}

// ---------------------------------------------------------------------------
// Exact u8 x s8 implicit-GEMM conv (9 shifts), mma.sync m16n8k32.
// CTA: 128 padded pixels (M) x 128 co (N). 8 warps = 2(M) x 4(N).
// ---------------------------------------------------------------------------
__global__ void __launch_bounds__(256, 2)
k_gconv(int plane, int wsel, int outsel) {
    __shared__ uint8_t sA[128 * 144];
    __shared__ uint8_t sB[128 * 144];
    const uint8_t* Aplane = g_planes + (size_t)plane * TOTS;
    const signed char* W  = wsel ? g_w2s : g_w1s;
    float* Out = (outsel == 0) ? g_c0 : ((outsel == 1) ? g_c1 : g_c2);

    const int tid = threadIdx.x, wid = tid >> 5, lane = tid & 31;
    const int n = blockIdx.x / NTILE, tile = blockIdx.x % NTILE;
    const int m0 = tile * 128;
    const int wm = (wid >> 2) * 64, wn = (wid & 3) * 32;
    const int gID = lane >> 2, tig = lane & 3;

    int acc[4][4][4];
    #pragma unroll
    for (int a = 0; a < 4; a++)
        #pragma unroll
        for (int b = 0; b < 4; b++)
            #pragma unroll
            for (int c = 0; c < 4; c++) acc[a][b][c] = 0;

    const uint8_t* base = Aplane + 8192 + (size_t)n * PIMG;
    const int crow = tid >> 1, chalf = tid & 1;

    #pragma unroll 1
    for (int sh = 0; sh < 9; ++sh) {
        const int ky = sh / 3, kx = sh % 3;
        const long long rowbase = (long long)m0 + (long long)(ky - 1) * 58 + (kx - 1);
        {
            const uint4* src = (const uint4*)(base + (rowbase + crow) * 128 + chalf * 64);
            uint4* dst = (uint4*)(sA + crow * 144 + chalf * 64);
            dst[0] = src[0]; dst[1] = src[1]; dst[2] = src[2]; dst[3] = src[3];
        }
        {
            const uint4* src = (const uint4*)(W + (size_t)sh * 16384 + crow * 128 + chalf * 64);
            uint4* dst = (uint4*)(sB + crow * 144 + chalf * 64);
            dst[0] = src[0]; dst[1] = src[1]; dst[2] = src[2]; dst[3] = src[3];
        }
        __syncthreads();
        #pragma unroll
        for (int ks = 0; ks < 4; ++ks) {
            uint32_t a[4][4], b[4][2];
            #pragma unroll
            for (int mf = 0; mf < 4; ++mf) {
                const uint8_t* p = sA + (wm + mf * 16 + gID) * 144 + ks * 32 + tig * 4;
                a[mf][0] = *(const uint32_t*)p;
                a[mf][1] = *(const uint32_t*)(p + 8 * 144);
                a[mf][2] = *(const uint32_t*)(p + 16);
                a[mf][3] = *(const uint32_t*)(p + 8 * 144 + 16);
            }
            #pragma unroll
            for (int nf = 0; nf < 4; ++nf) {
                const uint8_t* p = sB + (wn + nf * 8 + gID) * 144 + ks * 32 + tig * 4;
                b[nf][0] = *(const uint32_t*)p;
                b[nf][1] = *(const uint32_t*)(p + 16);
            }
            #pragma unroll
            for (int mf = 0; mf < 4; ++mf)
                #pragma unroll
                for (int nf = 0; nf < 4; ++nf)
                    imma(acc[mf][nf], a[mf], b[nf]);
        }
        __syncthreads();
    }

    float* obase = Out + (size_t)n * CIMG;
    #pragma unroll
    for (int mf = 0; mf < 4; ++mf) {
        int r0 = m0 + wm + mf * 16 + gID;
        int r1 = r0 + 8;
        #pragma unroll
        for (int nf = 0; nf < 4; ++nf) {
            int col = wn + nf * 8 + tig * 2;
            if (r0 < NPIX)
                *(float2*)(obase + (size_t)r0 * 128 + col) =
                    make_float2((float)acc[mf][nf][0], (float)acc[mf][nf][1]);
            if (r1 < NPIX)
                *(float2*)(obase + (size_t)r1 * 128 + col) =
                    make_float2((float)acc[mf][nf][2], (float)acc[mf][nf][3]);
        }
    }
}

// ---------------------------------------------------------------------------
// fp16 correction GEMM: corr = sum_k,ci x_fp16 * (delta*2^20). 18 stages
// (9 shifts x 2 ci-halves), same smem addressing as the u8 kernel.
// ---------------------------------------------------------------------------
__global__ void __launch_bounds__(256, 2)
k_gcorr() {
    __shared__ uint8_t sA[128 * 144];
    __shared__ uint8_t sB[128 * 144];
    const int tid = threadIdx.x, wid = tid >> 5, lane = tid & 31;
    const int n = blockIdx.x / NTILE, tile = blockIdx.x % NTILE;
    const int m0 = tile * 128;
    const int wm = (wid >> 2) * 64, wn = (wid & 3) * 32;
    const int gID = lane >> 2, tig = lane & 3;

    float acc[4][4][4];
    #pragma unroll
    for (int a = 0; a < 4; a++)
        #pragma unroll
        for (int b = 0; b < 4; b++)
            #pragma unroll
            for (int c = 0; c < 4; c++) acc[a][b][c] = 0.f;

    const uint8_t* baseA = (const uint8_t*)g_xh;   // halves
    const uint8_t* baseB = (const uint8_t*)g_w1d;
    const long long imgoff = 8192 + (long long)n * (long long)PIMG;
    const int crow = tid >> 1, chalf = tid & 1;

    #pragma unroll 1
    for (int st = 0; st < 18; ++st) {
        const int sh = st >> 1, hf = st & 1;
        const int ky = sh / 3, kx = sh % 3;
        const long long rowbase = (long long)m0 + (long long)(ky - 1) * 58 + (kx - 1);
        {   // A: 128 rows x 64 halves (128B)
            long long elem = imgoff + (rowbase + crow) * 128 + hf * 64;
            const uint4* src = (const uint4*)(baseA + elem * 2 + chalf * 64);
            uint4* dst = (uint4*)(sA + crow * 144 + chalf * 64);
            dst[0] = src[0]; dst[1] = src[1]; dst[2] = src[2]; dst[3] = src[3];
        }
        {   // B: [sh][co][ci] halves; co=crow, ci in [hf*64, hf*64+64)
            size_t elem = ((size_t)sh * Cc + crow) * Cc + hf * 64;
            const uint4* src = (const uint4*)(baseB + elem * 2 + chalf * 64);
            uint4* dst = (uint4*)(sB + crow * 144 + chalf * 64);
            dst[0] = src[0]; dst[1] = src[1]; dst[2] = src[2]; dst[3] = src[3];
        }
        __syncthreads();
        #pragma unroll
        for (int ks = 0; ks < 4; ++ks) {
            uint32_t a[4][4], b[4][2];
            #pragma unroll
            for (int mf = 0; mf < 4; ++mf) {
                const uint8_t* p = sA + (wm + mf * 16 + gID) * 144 + ks * 32 + tig * 4;
                a[mf][0] = *(const uint32_t*)p;
                a[mf][1] = *(const uint32_t*)(p + 8 * 144);
                a[mf][2] = *(const uint32_t*)(p + 16);
                a[mf][3] = *(const uint32_t*)(p + 8 * 144 + 16);
            }
            #pragma unroll
            for (int nf = 0; nf < 4; ++nf) {
                const uint8_t* p = sB + (wn + nf * 8 + gID) * 144 + ks * 32 + tig * 4;
                b[nf][0] = *(const uint32_t*)p;
                b[nf][1] = *(const uint32_t*)(p + 16);
            }
            #pragma unroll
            for (int mf = 0; mf < 4; ++mf)
                #pragma unroll
                for (int nf = 0; nf < 4; ++nf)
                    mmaf16(acc[mf][nf], a[mf], b[nf]);
        }
        __syncthreads();
    }

    float* obase = g_c3 + (size_t)n * CIMG;
    #pragma unroll
    for (int mf = 0; mf < 4; ++mf) {
        int r0 = m0 + wm + mf * 16 + gID;
        int r1 = r0 + 8;
        #pragma unroll
        for (int nf = 0; nf < 4; ++nf) {
            int col = wn + nf * 8 + tig * 2;
            if (r0 < NPIX)
                *(float2*)(obase + (size_t)r0 * 128 + col) =
                    make_float2(acc[mf][nf][0], acc[mf][nf][1]);
            if (r1 < NPIX)
                *(float2*)(obase + (size_t)r1 * 128 + col) =
                    make_float2(acc[mf][nf][2], acc[mf][nf][3]);
        }
    }
}

// per-channel double stats. mode 0: y1 (limbs+corr). mode 1: raw g_c0.
__global__ void k_statsr(int mode, int sidx) {
    const int n = blockIdx.y, seg = blockIdx.x, c = threadIdx.x;
    double s = 0.0, q = 0.0;
    for (int h = seg * 7; h < seg * 7 + 7; ++h)
        for (int w = 0; w < 56; ++w) {
            size_t pix = (size_t)(h + 1) * 58 + (w + 1);
            size_t off = (size_t)n * CIMG + pix * 128 + c;
            double v = (mode == 0) ? (double)combine_y1(off) : (double)g_c0[off];
            s += v; q += v * v;
        }
    atomicAdd(&g_sum[sidx][c], s);
    atomicAdd(&g_sq[sidx][c], q);
}

__global__ void k_stats(int pass) {
    int i = threadIdx.x;
    if (i >= Cc) return;
    double mu = g_sum[pass][i] / (double)NSTAT;
    double e2 = g_sq[pass][i] / (double)NSTAT;
    if (pass == 1) { mu /= 225.0; e2 /= 50625.0; }
    float muf = (float)mu;
    double var = e2 - 2.0 * (double)muf * mu + (double)muf * (double)muf;
    float denom = __fadd_rn((float)var, 1e-5f);
    g_mean[pass][i] = muf;
    g_rs[pass][i]   = (float)(1.0 / sqrt((double)denom));
}

// a1 levels = round(15*clip(bn1(y1),0,1)) -> u8 padded NHWC plane 3
__global__ void k_bnq(const float* __restrict__ gamma, const float* __restrict__ beta) {
    const int n = blockIdx.y, h = blockIdx.x;
    const int c = threadIdx.x & 127, ws = threadIdx.x >> 7;
    const float mean = g_mean[0][c], rs = g_rs[0][c];
    const float gm = gamma[c], bt = beta[c];
    uint8_t* ap = g_planes + 3ull * TOTS + 8192 + (size_t)n * PIMG;
    for (int w = ws; w < 56; w += 2) {
        size_t pix = (size_t)(h + 1) * 58 + (w + 1);
        size_t off = (size_t)n * CIMG + pix * 128 + c;
        float y = combine_y1(off);
        float xn  = __fmul_rn(__fadd_rn(y, -mean), rs);
        float bnv = __fadd_rn(__fmul_rn(xn, gm), bt);
        float cl  = fminf(fmaxf(bnv, 0.0f), 1.0f);
        ap[pix * 128 + c] = (uint8_t)(int)rintf(__fmul_rn(cl, 15.0f));
    }
}

// out = qfn(clip(bn2(S/225) + x, 0, 1)); NHWC->NCHW transpose via smem
__global__ void k_final(const float* __restrict__ gamma, const float* __restrict__ beta,
                        const float* __restrict__ x, float* __restrict__ outp) {
    __shared__ float s[32][33];
    const int n = blockIdx.z, h = blockIdx.y;
    const int w0 = (blockIdx.x & 1) * 32, c0 = (blockIdx.x >> 1) * 32;
    const int tx = threadIdx.x, ty = threadIdx.y;
    float v = 0.f;
    if (w0 + ty < 56) {
        size_t pix = (size_t)(h + 1) * 58 + (w0 + ty + 1);
        v = g_c0[(size_t)n * CIMG + pix * 128 + c0 + tx];
    }
    s[ty][tx] = v;
    __syncthreads();
    int w = w0 + tx, c = c0 + ty;
    if (w < 56) {
        float a = s[tx][ty];
        const float mean = g_mean[1][c], rs = g_rs[1][c];
        float y   = __fdiv_rn(a, 225.0f);
        float xn  = __fmul_rn(__fadd_rn(y, -mean), rs);
        float bnv = __fadd_rn(__fmul_rn(xn, gamma[c]), beta[c]);
        size_t oi = ((size_t)(n * Cc + c)) * HW + h * Ww + w;
        float vv  = __fadd_rn(bnv, x[oi]);
        float cl  = fminf(fmaxf(vv, 0.0f), 1.0f);
        outp[oi] = ste_quant(cl);
    }
}

// ---------------- launch ----------------
extern "C" void kernel_launch(void* const* d_in, const int* in_sizes, int n_in,
                              void* d_out, int out_size) {
    const float* x      = (const float*)d_in[0];
    const float* w1     = (const float*)d_in[1];
    const float* w2     = (const float*)d_in[2];
    const float* gamma1 = (const float*)d_in[3];
    const float* beta1  = (const float*)d_in[4];
    const float* gamma2 = (const float*)d_in[5];
    const float* beta2  = (const float*)d_in[6];
    float* outp = (float*)d_out;

    k_zero<<<1, 128>>>();
    k_zeroplanes<<<8192, 256>>>();

    dim3 wgrid(144, 2);
    k_maxabs<<<wgrid, 256>>>(w1, w2);
    k_quantw<<<wgrid, 256>>>(w1, w2);

    k_pack<<<dim3(8, Hh, Bn), dim3(32, 32)>>>(x);

    k_gconv<<<Bn * NTILE, 256>>>(0, 0, 0);   // conv1 limb0 -> g_c0
    k_gconv<<<Bn * NTILE, 256>>>(1, 0, 1);   // conv1 limb1 -> g_c1
    k_gconv<<<Bn * NTILE, 256>>>(2, 0, 2);   // conv1 limb2 -> g_c2
    k_gcorr<<<Bn * NTILE, 256>>>();          // conv1 STE-delta corr -> g_c3

    k_statsr<<<dim3(8, Bn), 128>>>(0, 0);
    k_stats<<<1, 128>>>(0);

    k_bnq<<<dim3(Hh, Bn), 256>>>(gamma1, beta1);

    k_gconv<<<Bn * NTILE, 256>>>(3, 1, 0);   // conv2 (exact int) -> g_c0

    k_statsr<<<dim3(8, Bn), 128>>>(1, 1);
    k_stats<<<1, 128>>>(1);

    k_final<<<dim3(8, Hh, Bn), dim3(32, 32)>>>(gamma2, beta2, x, outp);
}

// round 10
// speedup vs baseline: 1.6658x; 1.6658x over previous
#include <cuda_runtime.h>
#include <math.h>
#include <stdint.h>

// Problem constants
#define Bn   64
#define Cc   128
#define Hh   56
#define Ww   56
#define HW   3136            // Hh*Ww
#define NTOT 25690112        // Bn*Cc*HW
#define WN   147456          // Cc*Cc*9
#define NSTAT 200704         // Bn*HW
#define NC4  32              // Cc/4

// ---------------- device scratch ----------------
__device__ float   g_qw1[WN];        // conv1 fp32 quantized weights [ci][k][co]
__device__ int     g_w2p[NC4*9*Cc];  // conv2 s8 weights packed [ci4][k][co][4]
__device__ float   g_y1[NTOT];       // conv1 raw output
__device__ int     g_a1p[NTOT/4];    // a1 int levels packed [n][ci4][h][w][4]
__device__ float   g_y2[NTOT];       // conv2 integer accumulator (exact in fp32)
__device__ double  g_sum[2][Cc];
__device__ double  g_sq[2][Cc];
__device__ float   g_mean[2][Cc];
__device__ float   g_rs[2][Cc];
__device__ unsigned g_maxbits[2];

// ---------------- packed f32x2 helpers (sm_100+ base PTX) ----------------
__device__ __forceinline__ unsigned long long pk2(float lo, float hi) {
    unsigned long long r;
    asm("mov.b64 %0, {%1, %2};" : "=l"(r)
        : "r"(__float_as_uint(lo)), "r"(__float_as_uint(hi)));
    return r;
}
__device__ __forceinline__ void upk2(unsigned long long v, float& lo, float& hi) {
    uint32_t a, b;
    asm("mov.b64 {%0, %1}, %2;" : "=r"(a), "=r"(b) : "l"(v));
    lo = __uint_as_float(a); hi = __uint_as_float(b);
}
__device__ __forceinline__ unsigned long long fma2(unsigned long long a,
                                                   unsigned long long b,
                                                   unsigned long long c) {
    unsigned long long d;
    asm("fma.rn.f32x2 %0, %1, %2, %3;" : "=l"(d) : "l"(a), "l"(b), "l"(c));
    return d;
}
__device__ __forceinline__ unsigned long long add2(unsigned long long a,
                                                   unsigned long long b) {
    unsigned long long d;
    asm("add.rn.f32x2 %0, %1, %2;" : "=l"(d) : "l"(a), "l"(b));
    return d;
}

// ---------------- math helpers ----------------
__device__ __forceinline__ float xla_tanh(float x) {
    if (fabsf(x) < 0.0004f) return x;
    float xc = fminf(fmaxf(x, -7.90531110763549805f), 7.90531110763549805f);
    float x2 = __fmul_rn(xc, xc);
    float np = -2.76076847742355e-16f;
    np = fmaf(np, x2, 2.00018790482477e-13f);
    np = fmaf(np, x2, -8.60467152213735e-11f);
    np = fmaf(np, x2, 5.12229709037114e-08f);
    np = fmaf(np, x2, 1.48572235717979e-05f);
    np = fmaf(np, x2, 6.37261928875436e-04f);
    np = fmaf(np, x2, 4.89352455891786e-03f);
    np = __fmul_rn(xc, np);
    float dp = 1.19825839466702e-06f;
    dp = fmaf(dp, x2, 1.18534705686654e-04f);
    dp = fmaf(dp, x2, 2.26843463243900e-03f);
    dp = fmaf(dp, x2, 4.89352518554385e-03f);
    return __fdiv_rn(np, dp);
}
__device__ __forceinline__ float ste_quant(float c) {
    float q = __fdiv_rn(rintf(__fmul_rn(c, 15.0f)), 15.0f);
    return __fadd_rn(c, __fadd_rn(q, -c));
}

// ---------------- kernels ----------------
__global__ void k_zero() {
    int i = threadIdx.x;
    if (i < Cc) { g_sum[0][i]=0.0; g_sum[1][i]=0.0; g_sq[0][i]=0.0; g_sq[1][i]=0.0; }
    if (i < 2) g_maxbits[i] = 0u;
}

__global__ void k_maxabs(const float* __restrict__ w1,
                         const float* __restrict__ w2) {
    const int t = blockIdx.y;
    const float* w = t ? w2 : w1;
    float m = 0.0f;
    for (int i = blockIdx.x * blockDim.x + threadIdx.x; i < WN;
         i += gridDim.x * blockDim.x)
        m = fmaxf(m, fabsf(xla_tanh(w[i])));
    #pragma unroll
    for (int o = 16; o; o >>= 1) m = fmaxf(m, __shfl_xor_sync(0xffffffffu, m, o));
    if ((threadIdx.x & 31) == 0) atomicMax(&g_maxbits[t], __float_as_uint(m));
}

__global__ void k_quantw(const float* __restrict__ w1,
                         const float* __restrict__ w2) {
    const int t = blockIdx.y;
    const float* w = t ? w2 : w1;
    const float M = __uint_as_float(g_maxbits[t]);
    const float twoM = __fmul_rn(2.0f, M);
    for (int i = blockIdx.x * blockDim.x + threadIdx.x; i < WN;
         i += gridDim.x * blockDim.x) {
        float tv = xla_tanh(w[i]);
        float wn = __fadd_rn(__fdiv_rn(tv, twoM), 0.5f);
        int k = i % 9, ci = (i / 9) % Cc, co = i / (9 * Cc);
        if (t == 0) {
            float st = ste_quant(wn);
            float ov = __fadd_rn(__fmul_rn(2.0f, st), -1.0f);
            g_qw1[(ci * 9 + k) * Cc + co] = ov;
        } else {
            int lvl = (int)rintf(__fmul_rn(wn, 15.0f));
            signed char v = (signed char)(2 * lvl - 15);
            ((signed char*)g_w2p)[(((ci >> 2) * 9 + k) * Cc + co) * 4 + (ci & 3)] = v;
        }
    }
}

// ---------------------------------------------------------------------------
// conv1: fp32 direct 3x3 using packed fma.rn.f32x2 (2 IEEE FMAs per inst).
// Pairing over adjacent output channels; per-output FMA sequence identical to
// the scalar version -> bit-identical y1. Cascaded accumulation (4-ci groups).
// Thread = 8 co x 4 cols. Block (14,16). Grid (4, 16, 64). Fused BN stats.
// ---------------------------------------------------------------------------
#define TCO1 8
__global__ void __launch_bounds__(224, 2)
k_conv1(const float* __restrict__ xin) {
    const float* __restrict__ wT = g_qw1;
    const int n   = blockIdx.z;
    const int co0 = blockIdx.y * TCO1;
    const int h   = blockIdx.x * 16 + threadIdx.y;
    const int w0  = threadIdx.x * 4;
    const bool act = (h < Hh);

    // acc[copair][j]: packed (co even, co odd) fp32 pairs
    unsigned long long accm[4][4], acc2[4][4];
    const unsigned long long z2 = 0ull;
    #pragma unroll
    for (int cp = 0; cp < 4; cp++)
        #pragma unroll
        for (int j = 0; j < 4; j++) { accm[cp][j] = z2; acc2[cp][j] = z2; }

    if (act) {
        const bool r0ok = (h > 0);
        const bool r2ok = (h < Hh - 1);
        const bool c0ok = (w0 > 0);
        const bool c5ok = (w0 + 4 < Ww);
        const float* base = xin + (size_t)n * Cc * HW;

        #pragma unroll 1
        for (int ci = 0; ci < Cc; ci++) {
            const float* ip = base + (size_t)ci * HW;
            float xv[3][6];
            #pragma unroll
            for (int r = 0; r < 3; r++) {
                const int hh = h - 1 + r;
                const bool rok = (r == 0) ? r0ok : ((r == 2) ? r2ok : true);
                const float* rowp = ip + hh * Ww;
                float4 m = rok ? __ldg((const float4*)(rowp + w0))
                               : make_float4(0.f, 0.f, 0.f, 0.f);
                xv[r][1] = m.x; xv[r][2] = m.y; xv[r][3] = m.z; xv[r][4] = m.w;
                xv[r][0] = (rok && c0ok) ? __ldg(rowp + w0 - 1) : 0.0f;
                xv[r][5] = (rok && c5ok) ? __ldg(rowp + w0 + 4) : 0.0f;
            }
            // duplicate x values into lane pairs once per ci
            unsigned long long xd[3][6];
            #pragma unroll
            for (int r = 0; r < 3; r++)
                #pragma unroll
                for (int c = 0; c < 6; c++)
                    xd[r][c] = pk2(xv[r][c], xv[r][c]);

            const float* wp = wT + ci * 9 * Cc + co0;
            #pragma unroll
            for (int k = 0; k < 9; k++) {
                const int ky = k / 3, kx = k % 3;
                float4 wa = *(const float4*)(wp + k * Cc + 0);
                float4 wb = *(const float4*)(wp + k * Cc + 4);
                unsigned long long wpair[4];
                wpair[0] = pk2(wa.x, wa.y);
                wpair[1] = pk2(wa.z, wa.w);
                wpair[2] = pk2(wb.x, wb.y);
                wpair[3] = pk2(wb.z, wb.w);
                #pragma unroll
                for (int cp = 0; cp < 4; cp++)
                    #pragma unroll
                    for (int j = 0; j < 4; j++)
                        acc2[cp][j] = fma2(xd[ky][kx + j], wpair[cp], acc2[cp][j]);
            }
            if ((ci & 3) == 3) {   // flush 4-ci group (packed IEEE adds)
                #pragma unroll
                for (int cp = 0; cp < 4; cp++)
                    #pragma unroll
                    for (int j = 0; j < 4; j++) {
                        accm[cp][j] = add2(accm[cp][j], acc2[cp][j]);
                        acc2[cp][j] = z2;
                    }
            }
        }
    }

    // unpack accumulators to per-co floats
    float of[TCO1][4];
    #pragma unroll
    for (int cp = 0; cp < 4; cp++)
        #pragma unroll
        for (int j = 0; j < 4; j++)
            upk2(accm[cp][j], of[2 * cp][j], of[2 * cp + 1][j]);

    if (act) {
        #pragma unroll
        for (int c = 0; c < TCO1; c++) {
            float4 v = make_float4(of[c][0], of[c][1], of[c][2], of[c][3]);
            *(float4*)(g_y1 + (size_t)(n * Cc + co0 + c) * HW + h * Ww + w0) = v;
        }
    } else {
        #pragma unroll
        for (int c = 0; c < TCO1; c++)
            #pragma unroll
            for (int j = 0; j < 4; j++) of[c][j] = 0.f;
    }

    __shared__ double wsum[TCO1][7];
    __shared__ double wsq[TCO1][7];
    const int tid  = threadIdx.y * 14 + threadIdx.x;
    const int lane = tid & 31;
    const int wrp  = tid >> 5;
    #pragma unroll
    for (int c = 0; c < TCO1; c++) {
        double s = 0.0, q = 0.0;
        #pragma unroll
        for (int j = 0; j < 4; j++) {
            double v = (double)of[c][j];
            s += v; q += v * v;
        }
        #pragma unroll
        for (int o = 16; o; o >>= 1) {
            s += __shfl_down_sync(0xffffffffu, s, o);
            q += __shfl_down_sync(0xffffffffu, q, o);
        }
        if (lane == 0) { wsum[c][wrp] = s; wsq[c][wrp] = q; }
    }
    __syncthreads();
    if (tid < TCO1) {
        double s = 0.0, q = 0.0;
        #pragma unroll
        for (int k = 0; k < 7; k++) { s += wsum[tid][k]; q += wsq[tid][k]; }
        atomicAdd(&g_sum[0][co0 + tid], s);
        atomicAdd(&g_sq[0][co0 + tid], q);
    }
}

// ---------------------------------------------------------------------------
// conv2: EXACT int8 dp4a conv (unchanged from R5 best).
// ---------------------------------------------------------------------------
#define TCO2 16
__global__ void __launch_bounds__(224, 2)
k_conv2() {
    const int n   = blockIdx.z;
    const int co0 = blockIdx.y * TCO2;
    const int h   = blockIdx.x * 16 + threadIdx.y;
    const int w0  = threadIdx.x * 4;
    const bool act = (h < Hh);

    int acc[TCO2][4];
    #pragma unroll
    for (int c = 0; c < TCO2; c++)
        #pragma unroll
        for (int j = 0; j < 4; j++) acc[c][j] = 0;

    if (act) {
        const bool r0ok = (h > 0), r2ok = (h < Hh - 1);
        const bool c0ok = (w0 > 0), c5ok = (w0 + 4 < Ww);
        const int* base = g_a1p + (size_t)n * NC4 * HW;

        #pragma unroll 1
        for (int c4 = 0; c4 < NC4; c4++) {
            const int* ip = base + (size_t)c4 * HW;
            int xv[3][6];
            #pragma unroll
            for (int r = 0; r < 3; r++) {
                const int hh = h - 1 + r;
                const bool rok = (r == 0) ? r0ok : ((r == 2) ? r2ok : true);
                const int* rowp = ip + hh * Ww;
                int4 m = rok ? __ldg((const int4*)(rowp + w0)) : make_int4(0, 0, 0, 0);
                xv[r][1] = m.x; xv[r][2] = m.y; xv[r][3] = m.z; xv[r][4] = m.w;
                xv[r][0] = (rok && c0ok) ? __ldg(rowp + w0 - 1) : 0;
                xv[r][5] = (rok && c5ok) ? __ldg(rowp + w0 + 4) : 0;
            }
            const int* wp = g_w2p + (c4 * 9) * Cc + co0;
            #pragma unroll
            for (int k = 0; k < 9; k++) {
                const int ky = k / 3, kx = k % 3;
                int4 wa = *(const int4*)(wp + k * Cc + 0);
                int4 wb = *(const int4*)(wp + k * Cc + 4);
                int4 wc = *(const int4*)(wp + k * Cc + 8);
                int4 wd = *(const int4*)(wp + k * Cc + 12);
                int wr[16] = { wa.x, wa.y, wa.z, wa.w, wb.x, wb.y, wb.z, wb.w,
                               wc.x, wc.y, wc.z, wc.w, wd.x, wd.y, wd.z, wd.w };
                #pragma unroll
                for (int c = 0; c < TCO2; c++)
                    #pragma unroll
                    for (int j = 0; j < 4; j++)
                        acc[c][j] = __dp4a(xv[ky][kx + j], wr[c], acc[c][j]);
            }
        }

        #pragma unroll
        for (int c = 0; c < TCO2; c++) {
            float4 v = make_float4((float)acc[c][0], (float)acc[c][1],
                                   (float)acc[c][2], (float)acc[c][3]);
            *(float4*)(g_y2 + (size_t)(n * Cc + co0 + c) * HW + h * Ww + w0) = v;
        }
    }

    __shared__ double wsum[TCO2][7];
    __shared__ double wsq[TCO2][7];
    const int tid = threadIdx.y * 14 + threadIdx.x;
    const int lane = tid & 31, wrp = tid >> 5;
    #pragma unroll
    for (int c = 0; c < TCO2; c++) {
        double s = 0.0, q = 0.0;
        #pragma unroll
        for (int j = 0; j < 4; j++) {
            double v = (double)acc[c][j];
            s += v; q += v * v;
        }
        #pragma unroll
        for (int o = 16; o; o >>= 1) {
            s += __shfl_down_sync(0xffffffffu, s, o);
            q += __shfl_down_sync(0xffffffffu, q, o);
        }
        if (lane == 0) { wsum[c][wrp] = s; wsq[c][wrp] = q; }
    }
    __syncthreads();
    if (tid < TCO2) {
        double s = 0.0, q = 0.0;
        #pragma unroll
        for (int k = 0; k < 7; k++) { s += wsum[tid][k]; q += wsq[tid][k]; }
        atomicAdd(&g_sum[1][co0 + tid], s);
        atomicAdd(&g_sq[1][co0 + tid], q);
    }
}

__global__ void k_stats(int pass) {
    int i = threadIdx.x;
    if (i >= Cc) return;
    double mu = g_sum[pass][i] / (double)NSTAT;
    double e2 = g_sq[pass][i] / (double)NSTAT;
    if (pass == 1) { mu /= 225.0; e2 /= 50625.0; }
    float muf = (float)mu;
    double var = e2 - 2.0 * (double)muf * mu + (double)muf * (double)muf;
    float denom = __fadd_rn((float)var, 1e-5f);
    g_mean[pass][i] = muf;
    g_rs[pass][i]   = (float)(1.0 / sqrt((double)denom));
}

// a1 levels = round(15*clip(bn1(y1),0,1)), packed 4 channels/int32
__global__ void k_bnq(const float* __restrict__ gamma,
                      const float* __restrict__ beta) {
    int p = blockIdx.x * blockDim.x + threadIdx.x;
    if (p >= NTOT / 16) return;
    const int pix4 = p % (HW / 4);
    const int c4   = (p / (HW / 4)) % NC4;
    const int n    = p / (HW / 4) / NC4;
    const int off  = pix4 * 4;

    int out[4] = {0, 0, 0, 0};
    #pragma unroll
    for (int j = 0; j < 4; j++) {
        const int c = c4 * 4 + j;
        const float mean = g_mean[0][c], rs = g_rs[0][c];
        const float gm = gamma[c], bt = beta[c];
        float4 y = *(const float4*)(g_y1 + (size_t)(n * Cc + c) * HW + off);
        float v[4] = { y.x, y.y, y.z, y.w };
        #pragma unroll
        for (int w = 0; w < 4; w++) {
            float xn  = __fmul_rn(__fadd_rn(v[w], -mean), rs);
            float bnv = __fadd_rn(__fmul_rn(xn, gm), bt);
            float cl  = fminf(fmaxf(bnv, 0.0f), 1.0f);
            int lvl   = (int)rintf(__fmul_rn(cl, 15.0f));
            out[w] |= lvl << (8 * j);
        }
    }
    *(int4*)(g_a1p + (size_t)(n * NC4 + c4) * HW + off) =
        make_int4(out[0], out[1], out[2], out[3]);
}

// out = qfn(clip(bn2(acc/225) + x, 0, 1)) with ref STE value semantics
__global__ void k_final(const float* __restrict__ gamma,
                        const float* __restrict__ beta,
                        const float* __restrict__ x,
                        float* __restrict__ outp) {
    size_t i = ((size_t)blockIdx.x * blockDim.x + threadIdx.x) * 4;
    if (i >= (size_t)NTOT) return;
    int c = (int)((i / HW) % Cc);
    const float mean = g_mean[1][c], rs = g_rs[1][c];
    const float gm = gamma[c], bt = beta[c];
    float4 a  = *(const float4*)(g_y2 + i);
    float4 xr = *(const float4*)(x + i);
    float va[4] = { a.x, a.y, a.z, a.w };
    float vx[4] = { xr.x, xr.y, xr.z, xr.w };
    float r[4];
    #pragma unroll
    for (int j = 0; j < 4; j++) {
        float y   = __fdiv_rn(va[j], 225.0f);
        float xn  = __fmul_rn(__fadd_rn(y, -mean), rs);
        float bnv = __fadd_rn(__fmul_rn(xn, gm), bt);
        float vv  = __fadd_rn(bnv, vx[j]);
        float cl  = fminf(fmaxf(vv, 0.0f), 1.0f);
        r[j] = ste_quant(cl);
    }
    float4 o; o.x = r[0]; o.y = r[1]; o.z = r[2]; o.w = r[3];
    *(float4*)(outp + i) = o;
}

// ---------------- launch ----------------
extern "C" void kernel_launch(void* const* d_in, const int* in_sizes, int n_in,
                              void* d_out, int out_size) {
    const float* x      = (const float*)d_in[0];
    const float* w1     = (const float*)d_in[1];
    const float* w2     = (const float*)d_in[2];
    const float* gamma1 = (const float*)d_in[3];
    const float* beta1  = (const float*)d_in[4];
    const float* gamma2 = (const float*)d_in[5];
    const float* beta2  = (const float*)d_in[6];
    float* outp = (float*)d_out;

    k_zero<<<1, 128>>>();

    dim3 wgrid(144, 2);
    k_maxabs<<<wgrid, 256>>>(w1, w2);
    k_quantw<<<wgrid, 256>>>(w1, w2);

    dim3 cblock(14, 16);
    dim3 cgrid1(4, Cc / TCO1, Bn);
    dim3 cgrid2(4, Cc / TCO2, Bn);

    k_conv1<<<cgrid1, cblock>>>(x);
    k_stats<<<1, 128>>>(0);

    const int PB = 256;
    k_bnq<<<(NTOT / 16 + PB - 1) / PB, PB>>>(gamma1, beta1);

    k_conv2<<<cgrid2, cblock>>>();
    k_stats<<<1, 128>>>(1);

    const int EG = (NTOT / 4 + PB - 1) / PB;
    k_final<<<EG, PB>>>(gamma2, beta2, x, outp);
}